// round 1
// baseline (speedup 1.0000x reference)
#include <cuda_runtime.h>
#include <math.h>

// Problem constants
#define Bb 2
#define Tt 2048
#define Cc 4096
#define NH 32
#define NG 8
#define HS 128
#define QKV_D 6144      // (32 + 2*8) * 128
#define GRP_STRIDE 768  // 6 * 128 (4 q heads, 1 k, 1 v per group)

// Scratch (allocation-free rule: device globals)
__device__ float g_qkv[(size_t)Bb * Tt * QKV_D]; // 96 MB
__device__ float g_y[(size_t)Bb * Tt * Cc];      // 64 MB

// ---------------------------------------------------------------------------
// GEMM: C[M,N] = A[M,K] @ B[N,K]^T   (A, B row-major; M%128==0, N%128==0, K%16==0)
// 128x128 block, BK=16, 256 threads, 8x8 register tile per thread.
// ---------------------------------------------------------------------------
__global__ __launch_bounds__(256) void gemm_nt(const float* __restrict__ A,
                                               const float* __restrict__ B,
                                               float* __restrict__ C,
                                               int M, int N, int K) {
    __shared__ float As[16][128]; // [k][m]
    __shared__ float Bs[16][128]; // [k][n]

    const int tid = threadIdx.x;
    const int tx = tid & 15;
    const int ty = tid >> 4;
    const int bm = blockIdx.y << 7;
    const int bn = blockIdx.x << 7;

    const int lr = tid >> 2;        // 0..63
    const int lc = (tid & 3) << 2;  // 0,4,8,12

    float acc[8][8];
#pragma unroll
    for (int i = 0; i < 8; i++)
#pragma unroll
        for (int j = 0; j < 8; j++) acc[i][j] = 0.0f;

    const float* Aptr = A + (long)(bm + lr) * K + lc;
    const float* Bptr = B + (long)(bn + lr) * K + lc;
    const long rowK64 = (long)64 * K;

    for (int k0 = 0; k0 < K; k0 += 16) {
        float4 a0 = *(const float4*)(Aptr + k0);
        float4 a1 = *(const float4*)(Aptr + rowK64 + k0);
        float4 b0 = *(const float4*)(Bptr + k0);
        float4 b1 = *(const float4*)(Bptr + rowK64 + k0);

        As[lc + 0][lr] = a0.x; As[lc + 1][lr] = a0.y;
        As[lc + 2][lr] = a0.z; As[lc + 3][lr] = a0.w;
        As[lc + 0][lr + 64] = a1.x; As[lc + 1][lr + 64] = a1.y;
        As[lc + 2][lr + 64] = a1.z; As[lc + 3][lr + 64] = a1.w;

        Bs[lc + 0][lr] = b0.x; Bs[lc + 1][lr] = b0.y;
        Bs[lc + 2][lr] = b0.z; Bs[lc + 3][lr] = b0.w;
        Bs[lc + 0][lr + 64] = b1.x; Bs[lc + 1][lr + 64] = b1.y;
        Bs[lc + 2][lr + 64] = b1.z; Bs[lc + 3][lr + 64] = b1.w;

        __syncthreads();

#pragma unroll
        for (int kk = 0; kk < 16; kk++) {
            float a[8], b[8];
            *(float4*)&a[0] = *(const float4*)&As[kk][ty * 8];
            *(float4*)&a[4] = *(const float4*)&As[kk][ty * 8 + 4];
            *(float4*)&b[0] = *(const float4*)&Bs[kk][tx * 8];
            *(float4*)&b[4] = *(const float4*)&Bs[kk][tx * 8 + 4];
#pragma unroll
            for (int i = 0; i < 8; i++)
#pragma unroll
                for (int j = 0; j < 8; j++) acc[i][j] = fmaf(a[i], b[j], acc[i][j]);
        }
        __syncthreads();
    }

#pragma unroll
    for (int i = 0; i < 8; i++) {
        float* crow = C + (long)(bm + ty * 8 + i) * N + bn + tx * 8;
        *(float4*)(crow + 0) = make_float4(acc[i][0], acc[i][1], acc[i][2], acc[i][3]);
        *(float4*)(crow + 4) = make_float4(acc[i][4], acc[i][5], acc[i][6], acc[i][7]);
    }
}

// ---------------------------------------------------------------------------
// RoPE (in place on g_qkv): applied to 4 q-heads + 1 k-head per group.
// total threads = B*T*40*64  (40 roped heads per token, 64 rotation pairs)
// ---------------------------------------------------------------------------
__global__ __launch_bounds__(256) void rope_kernel(const float* __restrict__ cosp,
                                                   const float* __restrict__ sinp) {
    int idx = blockIdx.x * blockDim.x + threadIdx.x;
    int d = idx & 63;
    int r = idx >> 6;
    int hr = r % 40;           // roped head index within token
    int bt = r / 40;           // b*T + t
    int t = bt & (Tt - 1);
    int g = hr / 5, slot = hr % 5;  // slots 0..3 = q, 4 = k
    long base = (long)bt * QKV_D + g * GRP_STRIDE + slot * HS;

    float x1 = g_qkv[base + d];
    float x2 = g_qkv[base + d + 64];
    float c0 = cosp[t * HS + d],     s0 = sinp[t * HS + d];
    float c1 = cosp[t * HS + d + 64], s1 = sinp[t * HS + d + 64];
    g_qkv[base + d]      = x1 * c0 - x2 * s0;
    g_qkv[base + d + 64] = x2 * c1 + x1 * s1;
}

// ---------------------------------------------------------------------------
// Causal flash attention, fp32. BM = BN = 64, 256 threads.
// grid: (T/64, NH, B). Output into g_y[b, t, h*HS + d].
// Dynamic smem: Qs[128][64] + Ks[128][64] + Vs[64][128] + Ps[64][68]
// ---------------------------------------------------------------------------
#define FLASH_SMEM_FLOATS (8192 + 8192 + 8192 + 64 * 68)
#define FLASH_SMEM_BYTES (FLASH_SMEM_FLOATS * 4)

__global__ __launch_bounds__(256) void flash_kernel() {
    extern __shared__ float sm[];
    float* Qs = sm;              // [d][m] : 128 x 64
    float* Ks = sm + 8192;       // [d][n] : 128 x 64
    float* Vs = sm + 16384;      // [n][d] : 64 x 128
    float* Ps = sm + 24576;      // [n][m] : 64 x 68 (padded)

    const float scale = 0.08838834764831845f; // 1/sqrt(128)
    const int tid = threadIdx.x;
    const int tx = tid & 15;
    const int ty = tid >> 4;
    const int mblk = blockIdx.x;
    const int h = blockIdx.y;
    const int b = blockIdx.z;
    const int g = h >> 2, qslot = h & 3;
    const int m_start = mblk * 64;

    // Load Q tile (pre-scaled)
#pragma unroll
    for (int i = 0; i < 8; i++) {
        int f = tid + i * 256;
        int m = f >> 5;
        int d4 = (f & 31) * 4;
        const float4 q = *(const float4*)&g_qkv[(long)(b * Tt + m_start + m) * QKV_D +
                                                g * GRP_STRIDE + qslot * HS + d4];
        Qs[(d4 + 0) * 64 + m] = q.x * scale;
        Qs[(d4 + 1) * 64 + m] = q.y * scale;
        Qs[(d4 + 2) * 64 + m] = q.z * scale;
        Qs[(d4 + 3) * 64 + m] = q.w * scale;
    }

    float mi[4], li[4], O[4][8];
#pragma unroll
    for (int i = 0; i < 4; i++) {
        mi[i] = -1e30f;
        li[i] = 0.0f;
#pragma unroll
        for (int j = 0; j < 8; j++) O[i][j] = 0.0f;
    }

    for (int kb = 0; kb <= mblk; kb++) {
        const int n_start = kb * 64;
        // Load K (transposed) and V tiles
#pragma unroll
        for (int i = 0; i < 8; i++) {
            int f = tid + i * 256;
            int n = f >> 5;
            int d4 = (f & 31) * 4;
            long row = (long)(b * Tt + n_start + n) * QKV_D + g * GRP_STRIDE;
            float4 k4 = *(const float4*)&g_qkv[row + 4 * HS + d4];
            Ks[(d4 + 0) * 64 + n] = k4.x;
            Ks[(d4 + 1) * 64 + n] = k4.y;
            Ks[(d4 + 2) * 64 + n] = k4.z;
            Ks[(d4 + 3) * 64 + n] = k4.w;
            float4 v4 = *(const float4*)&g_qkv[row + 5 * HS + d4];
            *(float4*)&Vs[n * 128 + d4] = v4;
        }
        __syncthreads();

        // S = Qs^T Ks  (4x4 per thread)
        float s[4][4];
#pragma unroll
        for (int i = 0; i < 4; i++)
#pragma unroll
            for (int j = 0; j < 4; j++) s[i][j] = 0.0f;

#pragma unroll 4
        for (int d = 0; d < 128; d++) {
            float4 q4 = *(const float4*)&Qs[d * 64 + ty * 4];
            float4 k4 = *(const float4*)&Ks[d * 64 + tx * 4];
            float qa[4] = {q4.x, q4.y, q4.z, q4.w};
            float ka[4] = {k4.x, k4.y, k4.z, k4.w};
#pragma unroll
            for (int i = 0; i < 4; i++)
#pragma unroll
                for (int j = 0; j < 4; j++) s[i][j] = fmaf(qa[i], ka[j], s[i][j]);
        }

        // Causal mask on diagonal block
        if (kb == mblk) {
#pragma unroll
            for (int i = 0; i < 4; i++)
#pragma unroll
                for (int j = 0; j < 4; j++)
                    if (tx * 4 + j > ty * 4 + i) s[i][j] = -1e30f;
        }

        // Online softmax (rows split across 16 tx lanes; width-16 shuffles)
#pragma unroll
        for (int i = 0; i < 4; i++) {
            float mx = fmaxf(fmaxf(s[i][0], s[i][1]), fmaxf(s[i][2], s[i][3]));
#pragma unroll
            for (int off = 8; off > 0; off >>= 1)
                mx = fmaxf(mx, __shfl_xor_sync(0xffffffffu, mx, off, 16));
            float mnew = fmaxf(mi[i], mx);
            float alpha = expf(mi[i] - mnew);
            float rs = 0.0f;
#pragma unroll
            for (int j = 0; j < 4; j++) {
                s[i][j] = expf(s[i][j] - mnew);
                rs += s[i][j];
            }
#pragma unroll
            for (int off = 8; off > 0; off >>= 1)
                rs += __shfl_xor_sync(0xffffffffu, rs, off, 16);
            li[i] = li[i] * alpha + rs;
            mi[i] = mnew;
#pragma unroll
            for (int j = 0; j < 8; j++) O[i][j] *= alpha;
#pragma unroll
            for (int j = 0; j < 4; j++)
                Ps[(tx * 4 + j) * 68 + ty * 4 + i] = s[i][j];
        }
        __syncthreads();

        // O += P @ V   (rows ty*4.., cols tx*8..)
#pragma unroll 4
        for (int n = 0; n < 64; n++) {
            float4 p4 = *(const float4*)&Ps[n * 68 + ty * 4];
            float4 va = *(const float4*)&Vs[n * 128 + tx * 8];
            float4 vb = *(const float4*)&Vs[n * 128 + tx * 8 + 4];
            float v[8] = {va.x, va.y, va.z, va.w, vb.x, vb.y, vb.z, vb.w};
            float p[4] = {p4.x, p4.y, p4.z, p4.w};
#pragma unroll
            for (int i = 0; i < 4; i++)
#pragma unroll
                for (int j = 0; j < 8; j++) O[i][j] = fmaf(p[i], v[j], O[i][j]);
        }
        __syncthreads();
    }

    // Epilogue: normalize and write to g_y[b, t, h*HS + d]
#pragma unroll
    for (int i = 0; i < 4; i++) {
        float inv = 1.0f / li[i];
        int row = m_start + ty * 4 + i;
        float* yrow = g_y + (long)(b * Tt + row) * Cc + h * HS + tx * 8;
        *(float4*)(yrow + 0) = make_float4(O[i][0] * inv, O[i][1] * inv,
                                           O[i][2] * inv, O[i][3] * inv);
        *(float4*)(yrow + 4) = make_float4(O[i][4] * inv, O[i][5] * inv,
                                           O[i][6] * inv, O[i][7] * inv);
    }
}

// ---------------------------------------------------------------------------
// Launch
// ---------------------------------------------------------------------------
extern "C" void kernel_launch(void* const* d_in, const int* in_sizes, int n_in,
                              void* d_out, int out_size) {
    const float* x     = (const float*)d_in[0];
    const float* cosp  = (const float*)d_in[1];
    const float* sinp  = (const float*)d_in[2];
    const float* Wqkv  = (const float*)d_in[3];
    const float* Wproj = (const float*)d_in[4];
    float* out = (float*)d_out;

    void* qkv_p = nullptr;
    void* y_p = nullptr;
    cudaGetSymbolAddress(&qkv_p, g_qkv);
    cudaGetSymbolAddress(&y_p, g_y);

    cudaFuncSetAttribute(flash_kernel, cudaFuncAttributeMaxDynamicSharedMemorySize,
                         FLASH_SMEM_BYTES);

    // 1) qkv = x @ Wqkv^T : [4096, 4096] x [6144, 4096]^T
    gemm_nt<<<dim3(QKV_D / 128, (Bb * Tt) / 128), 256>>>(x, Wqkv, (float*)qkv_p,
                                                         Bb * Tt, QKV_D, Cc);
    // 2) RoPE in place on q and k heads
    rope_kernel<<<(Bb * Tt * 40 * 64) / 256, 256>>>(cosp, sinp);
    // 3) causal flash attention -> g_y
    flash_kernel<<<dim3(Tt / 64, NH, Bb), 256, FLASH_SMEM_BYTES>>>();
    // 4) out = y @ Wproj^T
    gemm_nt<<<dim3(Cc / 128, (Bb * Tt) / 128), 256>>>((const float*)y_p, Wproj, out,
                                                      Bb * Tt, Cc, Cc);
}

// round 3
// speedup vs baseline: 2.0994x; 2.0994x over previous
#include <cuda_runtime.h>
#include <math.h>
#include <stdint.h>

// Problem constants
#define Bb 2
#define Tt 2048
#define Cc 4096
#define NH 32
#define NG 8
#define HS 128
#define QKV_D 6144      // (32 + 2*8) * 128
#define GRP_STRIDE 768  // 6 * 128

// Scratch (allocation-free rule: device globals)
__device__ float g_qkv[(size_t)Bb * Tt * QKV_D];
__device__ float g_y[(size_t)Bb * Tt * Cc];
__device__ float g_xr[(size_t)Bb * Tt * Cc];
__device__ float g_wqkvr[(size_t)QKV_D * Cc];
__device__ float g_wprojr[(size_t)Cc * Cc];

// ---------------------------------------------------------------------------
// Helpers (portable: no sm_100a-only features — harness targets compute_100)
// ---------------------------------------------------------------------------
__device__ __forceinline__ uint32_t s2u(const void* p) {
    uint32_t a;
    asm("{ .reg .u64 t; cvta.to.shared.u64 t, %1; cvt.u32.u64 %0, t; }" : "=r"(a) : "l"(p));
    return a;
}
__device__ __forceinline__ void cpa16(uint32_t dst, const void* src) {
    asm volatile("cp.async.cg.shared.global [%0], [%1], 16;" :: "r"(dst), "l"(src));
}
__device__ __forceinline__ void mma_tf32(float* c, const uint32_t* a, const uint32_t* b) {
    asm volatile(
        "mma.sync.aligned.m16n8k8.row.col.f32.tf32.tf32.f32 "
        "{%0,%1,%2,%3}, {%4,%5,%6,%7}, {%8,%9}, {%0,%1,%2,%3};"
        : "+f"(c[0]), "+f"(c[1]), "+f"(c[2]), "+f"(c[3])
        : "r"(a[0]), "r"(a[1]), "r"(a[2]), "r"(a[3]), "r"(b[0]), "r"(b[1]));
}

// ---------------------------------------------------------------------------
// fp32 -> tf32 round-to-nearest pre-pass (out may alias in)
// ---------------------------------------------------------------------------
__global__ __launch_bounds__(256) void round_tf32(const float* __restrict__ in,
                                                  float* __restrict__ out, int n4) {
    int i = blockIdx.x * blockDim.x + threadIdx.x;
    if (i >= n4) return;
    float4 v = ((const float4*)in)[i];
    uint32_t a, b, c, d;
    asm("cvt.rna.tf32.f32 %0, %1;" : "=r"(a) : "f"(v.x));
    asm("cvt.rna.tf32.f32 %0, %1;" : "=r"(b) : "f"(v.y));
    asm("cvt.rna.tf32.f32 %0, %1;" : "=r"(c) : "f"(v.z));
    asm("cvt.rna.tf32.f32 %0, %1;" : "=r"(d) : "f"(v.w));
    v.x = __uint_as_float(a); v.y = __uint_as_float(b);
    v.z = __uint_as_float(c); v.w = __uint_as_float(d);
    ((float4*)out)[i] = v;
}

// ---------------------------------------------------------------------------
// TF32 warp-MMA GEMM: C[M,N] = A[M,K] @ B[N,K]^T   (row-major, pre-rounded)
// CTA 128x128, BK=32, 3-stage cp.async, 8 warps (4m x 2n), warp tile 32x64.
// Smem per stage: A 128x32f + B 128x32f = 32 KB; XOR swizzle (k ^= 4*(row&7)).
// ---------------------------------------------------------------------------
#define TS 3
#define STG_F 8192                 // floats per stage (A 4096 + B 4096)
#define GEMM_SMEM (TS * STG_F * 4) // 96 KB

__global__ __launch_bounds__(256, 2) void gemm_mma(const float* __restrict__ A,
                                                   const float* __restrict__ B,
                                                   float* __restrict__ C,
                                                   int M, int N, int K) {
    extern __shared__ float sm[];
    const uint32_t sb = s2u(sm);
    const int tid = threadIdx.x;
    const int wid = tid >> 5, lane = tid & 31;
    const int g = lane >> 2, t4 = lane & 3;
    const int warpM = wid & 3, warpN = wid >> 2;
    const int mbase = warpM * 32, nbase = warpN * 64;
    const int bm = blockIdx.y * 128;
    const int bn = blockIdx.x * 128;
    const int KT = K / 32;

    // load thread mapping: 4 chunks of A + 4 of B per thread per stage
    const int lr = tid >> 3;       // 0..31 (row block step 32)
    const int lc = tid & 7;        // 16B chunk in row

    auto load_tile = [&](int stage, int kt) {
        uint32_t a0 = sb + stage * (STG_F * 4);
        uint32_t b0 = a0 + 4096 * 4;
        const float* Ag = A + (size_t)(bm + lr) * K + (size_t)kt * 32 + lc * 4;
        const float* Bg = B + (size_t)(bn + lr) * K + (size_t)kt * 32 + lc * 4;
#pragma unroll
        for (int i = 0; i < 4; i++) {
            int r = lr + i * 32;
            uint32_t off = r * 128 + ((lc * 16) ^ ((r & 7) * 16));
            cpa16(a0 + off, Ag + (size_t)(i * 32) * K);
            cpa16(b0 + off, Bg + (size_t)(i * 32) * K);
        }
        asm volatile("cp.async.commit_group;" ::: "memory");
    };

    float c[2][8][4];
#pragma unroll
    for (int mi = 0; mi < 2; mi++)
#pragma unroll
        for (int nj = 0; nj < 8; nj++)
#pragma unroll
            for (int q = 0; q < 4; q++) c[mi][nj][q] = 0.0f;

    load_tile(0, 0);
    load_tile(1, 1);

    const int xr = g * 4; // XOR term (rows' &7 == g for all fragment rows)

    for (int kt = 0; kt < KT; kt++) {
        asm volatile("cp.async.wait_group %0;" :: "n"(TS - 2) : "memory");
        __syncthreads();

        if (kt + 2 < KT) load_tile((kt + 2) % TS, kt + 2);

        const float* As = sm + (kt % TS) * STG_F;
        const float* Bs = As + 4096;

#pragma unroll
        for (int ks = 0; ks < 4; ks++) {
            const int k0 = ks * 8;
            const int col0 = (k0 + t4) ^ xr;
            const int col1 = (k0 + t4 + 4) ^ xr;
            uint32_t a[2][4];
#pragma unroll
            for (int mi = 0; mi < 2; mi++) {
                int r0 = mbase + mi * 16 + g;
                a[mi][0] = __float_as_uint(As[r0 * 32 + col0]);
                a[mi][1] = __float_as_uint(As[(r0 + 8) * 32 + col0]);
                a[mi][2] = __float_as_uint(As[r0 * 32 + col1]);
                a[mi][3] = __float_as_uint(As[(r0 + 8) * 32 + col1]);
            }
            uint32_t b[8][2];
#pragma unroll
            for (int nj = 0; nj < 8; nj++) {
                int n = nbase + nj * 8 + g;
                b[nj][0] = __float_as_uint(Bs[n * 32 + col0]);
                b[nj][1] = __float_as_uint(Bs[n * 32 + col1]);
            }
#pragma unroll
            for (int mi = 0; mi < 2; mi++)
#pragma unroll
                for (int nj = 0; nj < 8; nj++) mma_tf32(c[mi][nj], a[mi], b[nj]);
        }
        __syncthreads();
    }

    // epilogue: write C from registers (float2 per fragment half)
#pragma unroll
    for (int mi = 0; mi < 2; mi++) {
        int r0 = bm + mbase + mi * 16 + g;
#pragma unroll
        for (int nj = 0; nj < 8; nj++) {
            int cc = bn + nbase + nj * 8 + 2 * t4;
            *(float2*)(C + (size_t)r0 * N + cc) = make_float2(c[mi][nj][0], c[mi][nj][1]);
            *(float2*)(C + (size_t)(r0 + 8) * N + cc) = make_float2(c[mi][nj][2], c[mi][nj][3]);
        }
    }
}

// ---------------------------------------------------------------------------
// RoPE (in place on g_qkv)
// ---------------------------------------------------------------------------
__global__ __launch_bounds__(256) void rope_kernel(const float* __restrict__ cosp,
                                                   const float* __restrict__ sinp) {
    int idx = blockIdx.x * blockDim.x + threadIdx.x;
    int d = idx & 63;
    int r = idx >> 6;
    int hr = r % 40;
    int bt = r / 40;
    int t = bt & (Tt - 1);
    int g = hr / 5, slot = hr % 5;
    long base = (long)bt * QKV_D + g * GRP_STRIDE + slot * HS;

    float x1 = g_qkv[base + d];
    float x2 = g_qkv[base + d + 64];
    float c0 = cosp[t * HS + d],      s0 = sinp[t * HS + d];
    float c1 = cosp[t * HS + d + 64], s1 = sinp[t * HS + d + 64];
    g_qkv[base + d]      = x1 * c0 - x2 * s0;
    g_qkv[base + d + 64] = x2 * c1 + x1 * s1;
}

// ---------------------------------------------------------------------------
// Causal flash attention, fp32 (unchanged)
// ---------------------------------------------------------------------------
#define FLASH_SMEM_FLOATS (8192 + 8192 + 8192 + 64 * 68)
#define FLASH_SMEM_BYTES (FLASH_SMEM_FLOATS * 4)

__global__ __launch_bounds__(256) void flash_kernel() {
    extern __shared__ float sm[];
    float* Qs = sm;
    float* Ks = sm + 8192;
    float* Vs = sm + 16384;
    float* Ps = sm + 24576;

    const float scale = 0.08838834764831845f;
    const int tid = threadIdx.x;
    const int tx = tid & 15;
    const int ty = tid >> 4;
    const int mblk = blockIdx.x;
    const int h = blockIdx.y;
    const int b = blockIdx.z;
    const int g = h >> 2, qslot = h & 3;
    const int m_start = mblk * 64;

#pragma unroll
    for (int i = 0; i < 8; i++) {
        int f = tid + i * 256;
        int m = f >> 5;
        int d4 = (f & 31) * 4;
        const float4 q = *(const float4*)&g_qkv[(long)(b * Tt + m_start + m) * QKV_D +
                                                g * GRP_STRIDE + qslot * HS + d4];
        Qs[(d4 + 0) * 64 + m] = q.x * scale;
        Qs[(d4 + 1) * 64 + m] = q.y * scale;
        Qs[(d4 + 2) * 64 + m] = q.z * scale;
        Qs[(d4 + 3) * 64 + m] = q.w * scale;
    }

    float mi[4], li[4], O[4][8];
#pragma unroll
    for (int i = 0; i < 4; i++) {
        mi[i] = -1e30f;
        li[i] = 0.0f;
#pragma unroll
        for (int j = 0; j < 8; j++) O[i][j] = 0.0f;
    }

    for (int kb = 0; kb <= mblk; kb++) {
        const int n_start = kb * 64;
#pragma unroll
        for (int i = 0; i < 8; i++) {
            int f = tid + i * 256;
            int n = f >> 5;
            int d4 = (f & 31) * 4;
            long row = (long)(b * Tt + n_start + n) * QKV_D + g * GRP_STRIDE;
            float4 k4 = *(const float4*)&g_qkv[row + 4 * HS + d4];
            Ks[(d4 + 0) * 64 + n] = k4.x;
            Ks[(d4 + 1) * 64 + n] = k4.y;
            Ks[(d4 + 2) * 64 + n] = k4.z;
            Ks[(d4 + 3) * 64 + n] = k4.w;
            float4 v4 = *(const float4*)&g_qkv[row + 5 * HS + d4];
            *(float4*)&Vs[n * 128 + d4] = v4;
        }
        __syncthreads();

        float s[4][4];
#pragma unroll
        for (int i = 0; i < 4; i++)
#pragma unroll
            for (int j = 0; j < 4; j++) s[i][j] = 0.0f;

#pragma unroll 4
        for (int d = 0; d < 128; d++) {
            float4 q4 = *(const float4*)&Qs[d * 64 + ty * 4];
            float4 k4 = *(const float4*)&Ks[d * 64 + tx * 4];
            float qa[4] = {q4.x, q4.y, q4.z, q4.w};
            float ka[4] = {k4.x, k4.y, k4.z, k4.w};
#pragma unroll
            for (int i = 0; i < 4; i++)
#pragma unroll
                for (int j = 0; j < 4; j++) s[i][j] = fmaf(qa[i], ka[j], s[i][j]);
        }

        if (kb == mblk) {
#pragma unroll
            for (int i = 0; i < 4; i++)
#pragma unroll
                for (int j = 0; j < 4; j++)
                    if (tx * 4 + j > ty * 4 + i) s[i][j] = -1e30f;
        }

#pragma unroll
        for (int i = 0; i < 4; i++) {
            float mx = fmaxf(fmaxf(s[i][0], s[i][1]), fmaxf(s[i][2], s[i][3]));
#pragma unroll
            for (int off = 8; off > 0; off >>= 1)
                mx = fmaxf(mx, __shfl_xor_sync(0xffffffffu, mx, off, 16));
            float mnew = fmaxf(mi[i], mx);
            float alpha = expf(mi[i] - mnew);
            float rs = 0.0f;
#pragma unroll
            for (int j = 0; j < 4; j++) {
                s[i][j] = expf(s[i][j] - mnew);
                rs += s[i][j];
            }
#pragma unroll
            for (int off = 8; off > 0; off >>= 1)
                rs += __shfl_xor_sync(0xffffffffu, rs, off, 16);
            li[i] = li[i] * alpha + rs;
            mi[i] = mnew;
#pragma unroll
            for (int j = 0; j < 8; j++) O[i][j] *= alpha;
#pragma unroll
            for (int j = 0; j < 4; j++)
                Ps[(tx * 4 + j) * 68 + ty * 4 + i] = s[i][j];
        }
        __syncthreads();

#pragma unroll 4
        for (int n = 0; n < 64; n++) {
            float4 p4 = *(const float4*)&Ps[n * 68 + ty * 4];
            float4 va = *(const float4*)&Vs[n * 128 + tx * 8];
            float4 vb = *(const float4*)&Vs[n * 128 + tx * 8 + 4];
            float v[8] = {va.x, va.y, va.z, va.w, vb.x, vb.y, vb.z, vb.w};
            float p[4] = {p4.x, p4.y, p4.z, p4.w};
#pragma unroll
            for (int i = 0; i < 4; i++)
#pragma unroll
                for (int j = 0; j < 8; j++) O[i][j] = fmaf(p[i], v[j], O[i][j]);
        }
        __syncthreads();
    }

#pragma unroll
    for (int i = 0; i < 4; i++) {
        float inv = 1.0f / li[i];
        int row = m_start + ty * 4 + i;
        float* yrow = g_y + (long)(b * Tt + row) * Cc + h * HS + tx * 8;
        *(float4*)(yrow + 0) = make_float4(O[i][0] * inv, O[i][1] * inv,
                                           O[i][2] * inv, O[i][3] * inv);
        *(float4*)(yrow + 4) = make_float4(O[i][4] * inv, O[i][5] * inv,
                                           O[i][6] * inv, O[i][7] * inv);
    }
}

// ---------------------------------------------------------------------------
// Launch
// ---------------------------------------------------------------------------
extern "C" void kernel_launch(void* const* d_in, const int* in_sizes, int n_in,
                              void* d_out, int out_size) {
    const float* x     = (const float*)d_in[0];
    const float* cosp  = (const float*)d_in[1];
    const float* sinp  = (const float*)d_in[2];
    const float* Wqkv  = (const float*)d_in[3];
    const float* Wproj = (const float*)d_in[4];
    float* out = (float*)d_out;

    void *qkv_p, *y_p, *xr_p, *wqkvr_p, *wprojr_p;
    cudaGetSymbolAddress(&qkv_p, g_qkv);
    cudaGetSymbolAddress(&y_p, g_y);
    cudaGetSymbolAddress(&xr_p, g_xr);
    cudaGetSymbolAddress(&wqkvr_p, g_wqkvr);
    cudaGetSymbolAddress(&wprojr_p, g_wprojr);

    cudaFuncSetAttribute(flash_kernel, cudaFuncAttributeMaxDynamicSharedMemorySize,
                         FLASH_SMEM_BYTES);
    cudaFuncSetAttribute(gemm_mma, cudaFuncAttributeMaxDynamicSharedMemorySize,
                         GEMM_SMEM);

    const int M = Bb * Tt;  // 4096

    // 0) tf32-round operands
    round_tf32<<<(M * Cc / 4) / 256, 256>>>(x, (float*)xr_p, M * Cc / 4);
    round_tf32<<<(QKV_D * Cc / 4) / 256, 256>>>(Wqkv, (float*)wqkvr_p, QKV_D * Cc / 4);
    round_tf32<<<(Cc * Cc / 4) / 256, 256>>>(Wproj, (float*)wprojr_p, Cc * Cc / 4);

    // 1) qkv = x @ Wqkv^T
    gemm_mma<<<dim3(QKV_D / 128, M / 128), 256, GEMM_SMEM>>>(
        (const float*)xr_p, (const float*)wqkvr_p, (float*)qkv_p, M, QKV_D, Cc);

    // 2) RoPE in place
    rope_kernel<<<(M * 40 * 64) / 256, 256>>>(cosp, sinp);

    // 3) causal flash attention -> g_y
    flash_kernel<<<dim3(Tt / 64, NH, Bb), 256, FLASH_SMEM_BYTES>>>();

    // 4) round y to tf32 in place, then out = y @ Wproj^T
    round_tf32<<<(M * Cc / 4) / 256, 256>>>((const float*)y_p, (float*)y_p, M * Cc / 4);
    gemm_mma<<<dim3(Cc / 128, M / 128), 256, GEMM_SMEM>>>(
        (const float*)y_p, (const float*)wprojr_p, out, M, Cc, Cc);
}

// round 6
// speedup vs baseline: 4.3814x; 2.0869x over previous
#include <cuda_runtime.h>
#include <math.h>
#include <stdint.h>

// Problem constants
#define Bb 2
#define Tt 2048
#define Cc 4096
#define NH 32
#define NG 8
#define HS 128
#define QKV_D 6144      // (32 + 2*8) * 128
#define GRP_STRIDE 768  // 6 * 128

// Scratch (allocation-free rule: device globals)
__device__ float g_qkv[(size_t)Bb * Tt * QKV_D];
__device__ float g_y[(size_t)Bb * Tt * Cc];
__device__ float g_xr[(size_t)Bb * Tt * Cc];
__device__ float g_wqkvr[(size_t)QKV_D * Cc];
__device__ float g_wprojr[(size_t)Cc * Cc];

// ---------------------------------------------------------------------------
// Helpers (portable: harness compiles through compute_100 — no tcgen05)
// ---------------------------------------------------------------------------
__device__ __forceinline__ uint32_t s2u(const void* p) {
    uint32_t a;
    asm("{ .reg .u64 t; cvta.to.shared.u64 t, %1; cvt.u32.u64 %0, t; }" : "=r"(a) : "l"(p));
    return a;
}
__device__ __forceinline__ void cpa16(uint32_t dst, const void* src) {
    asm volatile("cp.async.cg.shared.global [%0], [%1], 16;" :: "r"(dst), "l"(src));
}
__device__ __forceinline__ void mma_tf32(float* c, const uint32_t* a, uint32_t b0, uint32_t b1) {
    asm volatile(
        "mma.sync.aligned.m16n8k8.row.col.f32.tf32.tf32.f32 "
        "{%0,%1,%2,%3}, {%4,%5,%6,%7}, {%8,%9}, {%0,%1,%2,%3};"
        : "+f"(c[0]), "+f"(c[1]), "+f"(c[2]), "+f"(c[3])
        : "r"(a[0]), "r"(a[1]), "r"(a[2]), "r"(a[3]), "r"(b0), "r"(b1));
}
__device__ __forceinline__ float rnaf(float x) {
    uint32_t u;
    asm("cvt.rna.tf32.f32 %0, %1;" : "=r"(u) : "f"(x));
    return __uint_as_float(u);
}

// ---------------------------------------------------------------------------
// fp32 -> tf32 round-to-nearest pre-pass (out may alias in)
// ---------------------------------------------------------------------------
__global__ __launch_bounds__(256) void round_tf32(const float* __restrict__ in,
                                                  float* __restrict__ out, int n4) {
    int i = blockIdx.x * blockDim.x + threadIdx.x;
    if (i >= n4) return;
    float4 v = ((const float4*)in)[i];
    v.x = rnaf(v.x); v.y = rnaf(v.y); v.z = rnaf(v.z); v.w = rnaf(v.w);
    ((float4*)out)[i] = v;
}

// ---------------------------------------------------------------------------
// TF32 warp-MMA GEMM: C[M,N] = A[M,K] @ B[N,K]^T   (row-major, pre-rounded)
// CTA 128x128, BK=32, 3-stage cp.async, 8 warps (4m x 2n), warp tile 32x64.
// ---------------------------------------------------------------------------
#define TS 3
#define STG_F 8192
#define GEMM_SMEM (TS * STG_F * 4)

__global__ __launch_bounds__(256, 2) void gemm_mma(const float* __restrict__ A,
                                                   const float* __restrict__ B,
                                                   float* __restrict__ C,
                                                   int M, int N, int K) {
    extern __shared__ float sm[];
    const uint32_t sb = s2u(sm);
    const int tid = threadIdx.x;
    const int wid = tid >> 5, lane = tid & 31;
    const int g = lane >> 2, t4 = lane & 3;
    const int warpM = wid & 3, warpN = wid >> 2;
    const int mbase = warpM * 32, nbase = warpN * 64;
    const int bm = blockIdx.y * 128;
    const int bn = blockIdx.x * 128;
    const int KT = K / 32;

    const int lr = tid >> 3;
    const int lc = tid & 7;

    auto load_tile = [&](int stage, int kt) {
        uint32_t a0 = sb + stage * (STG_F * 4);
        uint32_t b0 = a0 + 4096 * 4;
        const float* Ag = A + (size_t)(bm + lr) * K + (size_t)kt * 32 + lc * 4;
        const float* Bg = B + (size_t)(bn + lr) * K + (size_t)kt * 32 + lc * 4;
#pragma unroll
        for (int i = 0; i < 4; i++) {
            int r = lr + i * 32;
            uint32_t off = r * 128 + ((lc * 16) ^ ((r & 7) * 16));
            cpa16(a0 + off, Ag + (size_t)(i * 32) * K);
            cpa16(b0 + off, Bg + (size_t)(i * 32) * K);
        }
        asm volatile("cp.async.commit_group;" ::: "memory");
    };

    float c[2][8][4];
#pragma unroll
    for (int mi = 0; mi < 2; mi++)
#pragma unroll
        for (int nj = 0; nj < 8; nj++)
#pragma unroll
            for (int q = 0; q < 4; q++) c[mi][nj][q] = 0.0f;

    load_tile(0, 0);
    load_tile(1, 1);

    const int xr = g * 4;

    for (int kt = 0; kt < KT; kt++) {
        asm volatile("cp.async.wait_group %0;" :: "n"(TS - 2) : "memory");
        __syncthreads();

        if (kt + 2 < KT) load_tile((kt + 2) % TS, kt + 2);

        const float* As = sm + (kt % TS) * STG_F;
        const float* Bs = As + 4096;

#pragma unroll
        for (int ks = 0; ks < 4; ks++) {
            const int k0 = ks * 8;
            const int col0 = (k0 + t4) ^ xr;
            const int col1 = (k0 + t4 + 4) ^ xr;
            uint32_t a[2][4];
#pragma unroll
            for (int mi = 0; mi < 2; mi++) {
                int r0 = mbase + mi * 16 + g;
                a[mi][0] = __float_as_uint(As[r0 * 32 + col0]);
                a[mi][1] = __float_as_uint(As[(r0 + 8) * 32 + col0]);
                a[mi][2] = __float_as_uint(As[r0 * 32 + col1]);
                a[mi][3] = __float_as_uint(As[(r0 + 8) * 32 + col1]);
            }
            uint32_t b[8][2];
#pragma unroll
            for (int nj = 0; nj < 8; nj++) {
                int n = nbase + nj * 8 + g;
                b[nj][0] = __float_as_uint(Bs[n * 32 + col0]);
                b[nj][1] = __float_as_uint(Bs[n * 32 + col1]);
            }
#pragma unroll
            for (int mi = 0; mi < 2; mi++)
#pragma unroll
                for (int nj = 0; nj < 8; nj++) mma_tf32(c[mi][nj], a[mi], b[nj][0], b[nj][1]);
        }
        __syncthreads();
    }

#pragma unroll
    for (int mi = 0; mi < 2; mi++) {
        int r0 = bm + mbase + mi * 16 + g;
#pragma unroll
        for (int nj = 0; nj < 8; nj++) {
            int cc = bn + nbase + nj * 8 + 2 * t4;
            *(float2*)(C + (size_t)r0 * N + cc) = make_float2(c[mi][nj][0], c[mi][nj][1]);
            *(float2*)(C + (size_t)(r0 + 8) * N + cc) = make_float2(c[mi][nj][2], c[mi][nj][3]);
        }
    }
}

// ---------------------------------------------------------------------------
// RoPE (in place on g_qkv)
// ---------------------------------------------------------------------------
__global__ __launch_bounds__(256) void rope_kernel(const float* __restrict__ cosp,
                                                   const float* __restrict__ sinp) {
    int idx = blockIdx.x * blockDim.x + threadIdx.x;
    int d = idx & 63;
    int r = idx >> 6;
    int hr = r % 40;
    int bt = r / 40;
    int t = bt & (Tt - 1);
    int g = hr / 5, slot = hr % 5;
    long base = (long)bt * QKV_D + g * GRP_STRIDE + slot * HS;

    float x1 = g_qkv[base + d];
    float x2 = g_qkv[base + d + 64];
    float c0 = cosp[t * HS + d],      s0 = sinp[t * HS + d];
    float c1 = cosp[t * HS + d + 64], s1 = sinp[t * HS + d + 64];
    g_qkv[base + d]      = x1 * c0 - x2 * s0;
    g_qkv[base + d + 64] = x2 * c1 + x1 * s1;
}

// ---------------------------------------------------------------------------
// Tensor-core causal flash attention (tf32 MMA).
// BM=128 (8 warps x 16 rows), BN=64, D=128, 256 threads.
// Q fragments in registers; K smem [64][132]; V smem [64][136];
// P per-warp smem [16 rows][68]. Fused tf32-rna on output write.
// ---------------------------------------------------------------------------
#define KS_OFF 0
#define VS_OFF 8448               // 64*132
#define PS_OFF 17152              // + 64*136
#define FLASH2_SMEM_F 25856       // + 128*68
#define FLASH2_SMEM_BYTES (FLASH2_SMEM_F * 4)

__global__ __launch_bounds__(256, 1) void flash_mma() {
    extern __shared__ float sm[];
    float* Ks = sm + KS_OFF;
    float* Vs = sm + VS_OFF;
    float* Ps = sm + PS_OFF;

    const float scale = 0.08838834764831845f; // 1/sqrt(128)
    const int tid = threadIdx.x;
    const int lane = tid & 31;
    const int wid = tid >> 5;
    const int g = lane >> 2, t4 = lane & 3;
    const int mbase = wid * 16;
    const int mblk = blockIdx.x;
    const int h = blockIdx.y;
    const int b = blockIdx.z;
    const int grp = h >> 2, qslot = h & 3;
    const int m_start = mblk * 128;
    const long bT = (long)b * Tt;

    // --- Q fragments in registers (rna + pre-scale), rows mbase+g / +8
    uint32_t q[16][4];
    {
        const float* q0 = &g_qkv[(bT + m_start + mbase + g) * QKV_D +
                                 grp * GRP_STRIDE + qslot * HS];
        const float* q1 = q0 + 8L * QKV_D;
#pragma unroll
        for (int ks = 0; ks < 16; ks++) {
            q[ks][0] = __float_as_uint(rnaf(q0[ks * 8 + t4] * scale));
            q[ks][1] = __float_as_uint(rnaf(q1[ks * 8 + t4] * scale));
            q[ks][2] = __float_as_uint(rnaf(q0[ks * 8 + t4 + 4] * scale));
            q[ks][3] = __float_as_uint(rnaf(q1[ks * 8 + t4 + 4] * scale));
        }
    }

    float o[16][4];
#pragma unroll
    for (int nt = 0; nt < 16; nt++)
#pragma unroll
        for (int j = 0; j < 4; j++) o[nt][j] = 0.0f;
    float m0 = -1e30f, m1 = -1e30f, l0 = 0.0f, l1 = 0.0f;

    const int row0 = m_start + mbase + g;
    const int row1 = row0 + 8;
    const int KB = 2 * mblk + 2;

    for (int kb = 0; kb < KB; kb++) {
        const int n_start = kb * 64;

        __syncthreads();  // all warps done reading previous K/V
        // --- load K,V tile (rna-rounded)
#pragma unroll
        for (int i = 0; i < 8; i++) {
            int f = tid + i * 256;
            int kv = f >> 5;
            int d4 = (f & 31) * 4;
            const float* rowp = &g_qkv[(bT + n_start + kv) * QKV_D + grp * GRP_STRIDE];
            float4 k4 = *(const float4*)(rowp + 4 * HS + d4);
            k4.x = rnaf(k4.x); k4.y = rnaf(k4.y); k4.z = rnaf(k4.z); k4.w = rnaf(k4.w);
            *(float4*)&Ks[kv * 132 + d4] = k4;
            float4 v4 = *(const float4*)(rowp + 5 * HS + d4);
            v4.x = rnaf(v4.x); v4.y = rnaf(v4.y); v4.z = rnaf(v4.z); v4.w = rnaf(v4.w);
            *(float4*)&Vs[kv * 136 + d4] = v4;
        }
        __syncthreads();

        // --- S = Q @ K^T  (16 k-steps x 8 n-tiles)
        float s[8][4];
#pragma unroll
        for (int nt = 0; nt < 8; nt++)
#pragma unroll
            for (int j = 0; j < 4; j++) s[nt][j] = 0.0f;

#pragma unroll
        for (int ks = 0; ks < 16; ks++) {
#pragma unroll
            for (int nt = 0; nt < 8; nt++) {
                const float* kp = &Ks[(nt * 8 + g) * 132 + ks * 8 + t4];
                mma_tf32(s[nt], q[ks], __float_as_uint(kp[0]), __float_as_uint(kp[4]));
            }
        }

        // --- causal mask (only the last two blocks can touch the diagonal)
        if (kb >= 2 * mblk) {
#pragma unroll
            for (int nt = 0; nt < 8; nt++) {
                int c0 = n_start + nt * 8 + 2 * t4;
                if (c0 > row0) s[nt][0] = -1e30f;
                if (c0 + 1 > row0) s[nt][1] = -1e30f;
                if (c0 > row1) s[nt][2] = -1e30f;
                if (c0 + 1 > row1) s[nt][3] = -1e30f;
            }
        }

        // --- online softmax (rows live in 4 lanes: xor 1,2 reductions)
        float bm0 = -1e30f, bm1 = -1e30f;
#pragma unroll
        for (int nt = 0; nt < 8; nt++) {
            bm0 = fmaxf(bm0, fmaxf(s[nt][0], s[nt][1]));
            bm1 = fmaxf(bm1, fmaxf(s[nt][2], s[nt][3]));
        }
        bm0 = fmaxf(bm0, __shfl_xor_sync(0xffffffffu, bm0, 1));
        bm0 = fmaxf(bm0, __shfl_xor_sync(0xffffffffu, bm0, 2));
        bm1 = fmaxf(bm1, __shfl_xor_sync(0xffffffffu, bm1, 1));
        bm1 = fmaxf(bm1, __shfl_xor_sync(0xffffffffu, bm1, 2));

        float mn0 = fmaxf(m0, bm0), mn1 = fmaxf(m1, bm1);
        float a0 = __expf(m0 - mn0), a1 = __expf(m1 - mn1);
#pragma unroll
        for (int nt = 0; nt < 16; nt++) {
            o[nt][0] *= a0; o[nt][1] *= a0;
            o[nt][2] *= a1; o[nt][3] *= a1;
        }

        float rs0 = 0.0f, rs1 = 0.0f;
#pragma unroll
        for (int nt = 0; nt < 8; nt++) {
            float p0 = __expf(s[nt][0] - mn0);
            float p1 = __expf(s[nt][1] - mn0);
            float p2 = __expf(s[nt][2] - mn1);
            float p3 = __expf(s[nt][3] - mn1);
            rs0 += p0 + p1;
            rs1 += p2 + p3;
            *(float2*)&Ps[(mbase + g) * 68 + nt * 8 + 2 * t4] =
                make_float2(rnaf(p0), rnaf(p1));
            *(float2*)&Ps[(mbase + g + 8) * 68 + nt * 8 + 2 * t4] =
                make_float2(rnaf(p2), rnaf(p3));
        }
        rs0 += __shfl_xor_sync(0xffffffffu, rs0, 1);
        rs0 += __shfl_xor_sync(0xffffffffu, rs0, 2);
        rs1 += __shfl_xor_sync(0xffffffffu, rs1, 1);
        rs1 += __shfl_xor_sync(0xffffffffu, rs1, 2);
        l0 = l0 * a0 + rs0;
        l1 = l1 * a1 + rs1;
        m0 = mn0; m1 = mn1;

        __syncwarp();  // P slice is per-warp: stores visible to own lanes

        // --- O += P @ V  (8 k-steps x 16 n-tiles)
#pragma unroll
        for (int ks = 0; ks < 8; ks++) {
            uint32_t a[4];
            a[0] = __float_as_uint(Ps[(mbase + g) * 68 + ks * 8 + t4]);
            a[1] = __float_as_uint(Ps[(mbase + g + 8) * 68 + ks * 8 + t4]);
            a[2] = __float_as_uint(Ps[(mbase + g) * 68 + ks * 8 + t4 + 4]);
            a[3] = __float_as_uint(Ps[(mbase + g + 8) * 68 + ks * 8 + t4 + 4]);
#pragma unroll
            for (int nt = 0; nt < 16; nt++) {
                const float* vp = &Vs[(ks * 8 + t4) * 136 + nt * 8 + g];
                mma_tf32(o[nt], a, __float_as_uint(vp[0]), __float_as_uint(vp[4 * 136]));
            }
        }
    }

    // --- epilogue: O/l, rna-rounded (feeds tf32 proj GEMM directly)
    const float i0 = 1.0f / l0, i1 = 1.0f / l1;
    float* y0 = g_y + (bT + row0) * Cc + h * HS;
    float* y1 = g_y + (bT + row1) * Cc + h * HS;
#pragma unroll
    for (int nt = 0; nt < 16; nt++) {
        int cc = nt * 8 + 2 * t4;
        *(float2*)(y0 + cc) = make_float2(rnaf(o[nt][0] * i0), rnaf(o[nt][1] * i0));
        *(float2*)(y1 + cc) = make_float2(rnaf(o[nt][2] * i1), rnaf(o[nt][3] * i1));
    }
}

// ---------------------------------------------------------------------------
// Launch
// ---------------------------------------------------------------------------
extern "C" void kernel_launch(void* const* d_in, const int* in_sizes, int n_in,
                              void* d_out, int out_size) {
    const float* x     = (const float*)d_in[0];
    const float* cosp  = (const float*)d_in[1];
    const float* sinp  = (const float*)d_in[2];
    const float* Wqkv  = (const float*)d_in[3];
    const float* Wproj = (const float*)d_in[4];
    float* out = (float*)d_out;

    void *qkv_p, *y_p, *xr_p, *wqkvr_p, *wprojr_p;
    cudaGetSymbolAddress(&qkv_p, g_qkv);
    cudaGetSymbolAddress(&y_p, g_y);
    cudaGetSymbolAddress(&xr_p, g_xr);
    cudaGetSymbolAddress(&wqkvr_p, g_wqkvr);
    cudaGetSymbolAddress(&wprojr_p, g_wprojr);

    cudaFuncSetAttribute(gemm_mma, cudaFuncAttributeMaxDynamicSharedMemorySize,
                         GEMM_SMEM);
    cudaFuncSetAttribute(flash_mma, cudaFuncAttributeMaxDynamicSharedMemorySize,
                         FLASH2_SMEM_BYTES);

    const int M = Bb * Tt;  // 4096

    // 0) tf32-round GEMM operands
    round_tf32<<<(M * Cc / 4) / 256, 256>>>(x, (float*)xr_p, M * Cc / 4);
    round_tf32<<<(QKV_D * Cc / 4) / 256, 256>>>(Wqkv, (float*)wqkvr_p, QKV_D * Cc / 4);
    round_tf32<<<(Cc * Cc / 4) / 256, 256>>>(Wproj, (float*)wprojr_p, Cc * Cc / 4);

    // 1) qkv = x @ Wqkv^T
    gemm_mma<<<dim3(QKV_D / 128, M / 128), 256, GEMM_SMEM>>>(
        (const float*)xr_p, (const float*)wqkvr_p, (float*)qkv_p, M, QKV_D, Cc);

    // 2) RoPE in place
    rope_kernel<<<(M * 40 * 64) / 256, 256>>>(cosp, sinp);

    // 3) tensor-core causal flash attention -> g_y (rna-rounded)
    flash_mma<<<dim3(Tt / 128, NH, Bb), 256, FLASH2_SMEM_BYTES>>>();

    // 4) out = y @ Wproj^T
    gemm_mma<<<dim3(Cc / 128, M / 128), 256, GEMM_SMEM>>>(
        (const float*)y_p, (const float*)wprojr_p, out, M, Cc, Cc);
}